// round 1
// baseline (speedup 1.0000x reference)
#include <cuda_runtime.h>
#include <math.h>

#define NN 50000
#define NE 500000

// ---------------- scratch (static device globals; no allocation) ----------------
__device__ float    g_Q[(size_t)NN * 128];
__device__ float    g_K[(size_t)NN * 128];
__device__ float    g_V[(size_t)NN * 128];
__device__ float    g_Ee[(size_t)NE * 128];
__device__ float    g_score[(size_t)NE * 8];
__device__ float    g_ex[(size_t)NE * 8];
__device__ unsigned g_segmax[(size_t)NN * 8];
__device__ float    g_denom[(size_t)NN * 8];

// ---------------- helpers ----------------
__device__ __forceinline__ unsigned enc_f(float f) {
    unsigned u = __float_as_uint(f);
    return (u & 0x80000000u) ? ~u : (u | 0x80000000u);
}
__device__ __forceinline__ float dec_f(unsigned e) {
    return __uint_as_float((e & 0x80000000u) ? (e ^ 0x80000000u) : ~e);
}

// ---------------- GEMM: C[rows,128] = A[rows,128] @ W[128,128] + bias ----------------
// 128x128 block tile, 256 threads, 8x8 per-thread microtile, packed f32x2 FMA.
#define ASTR 133
#define GEMM_SMEM_BYTES ((128 * 128 + 128 * ASTR) * 4)

extern __shared__ float smem_f[];

__global__ __launch_bounds__(256, 1) void gemm128(const float* __restrict__ A,
                                                  const float* __restrict__ W,
                                                  const float* __restrict__ bias,
                                                  float* __restrict__ C, int rows) {
    float* Bs = smem_f;               // [128][128] W as (k, n)
    float* At = smem_f + 128 * 128;   // [128][ASTR] A transposed: (k, row)
    const int tid = threadIdx.x;
    const int r0 = blockIdx.x * 128;

    // load W (16384 floats) with float4
    {
        const float4* W4 = (const float4*)W;
        float4* Bs4 = (float4*)Bs;
#pragma unroll
        for (int i = 0; i < 16; i++) Bs4[tid + 256 * i] = W4[tid + 256 * i];
    }
    // load A tile transposed, scalar (coalesced gmem, conflict-free STS: bank = 5k+row)
#pragma unroll 8
    for (int i = 0; i < 64; i++) {
        int l = tid + 256 * i;
        int k = l & 127;
        int row = l >> 7;
        float v = 0.0f;
        if (r0 + row < rows) v = A[(size_t)(r0 + row) * 128 + k];
        At[k * ASTR + row] = v;
    }
    __syncthreads();

    const int tx = tid & 15;   // col group: cols 8*tx .. 8*tx+7
    const int ty = tid >> 4;   // row group: rows 8*ty .. 8*ty+7

    unsigned long long acc[8][4];
#pragma unroll
    for (int i = 0; i < 8; i++)
#pragma unroll
        for (int p = 0; p < 4; p++) acc[i][p] = 0ull;

    const float* atp = At + ty * 8;
    const float* bp = Bs + tx * 8;

#pragma unroll 8
    for (int k = 0; k < 128; k++) {
        ulonglong2 b01 = *(const ulonglong2*)(bp + k * 128);
        ulonglong2 b23 = *(const ulonglong2*)(bp + k * 128 + 4);
#pragma unroll
        for (int i = 0; i < 8; i++) {
            unsigned ab = __float_as_uint(atp[k * ASTR + i]);
            unsigned long long ad;
            asm("mov.b64 %0, {%1, %2};" : "=l"(ad) : "r"(ab), "r"(ab));
            asm("fma.rn.f32x2 %0, %1, %2, %0;" : "+l"(acc[i][0]) : "l"(ad), "l"(b01.x));
            asm("fma.rn.f32x2 %0, %1, %2, %0;" : "+l"(acc[i][1]) : "l"(ad), "l"(b01.y));
            asm("fma.rn.f32x2 %0, %1, %2, %0;" : "+l"(acc[i][2]) : "l"(ad), "l"(b23.x));
            asm("fma.rn.f32x2 %0, %1, %2, %0;" : "+l"(acc[i][3]) : "l"(ad), "l"(b23.y));
        }
    }

    float4 bb0 = *(const float4*)(bias + tx * 8);
    float4 bb1 = *(const float4*)(bias + tx * 8 + 4);

#pragma unroll
    for (int i = 0; i < 8; i++) {
        int row = r0 + ty * 8 + i;
        if (row < rows) {
            unsigned lo, hi;
            float c[8];
#pragma unroll
            for (int p = 0; p < 4; p++) {
                asm("mov.b64 {%0, %1}, %2;" : "=r"(lo), "=r"(hi) : "l"(acc[i][p]));
                c[2 * p] = __uint_as_float(lo);
                c[2 * p + 1] = __uint_as_float(hi);
            }
            float4 o0 = make_float4(c[0] + bb0.x, c[1] + bb0.y, c[2] + bb0.z, c[3] + bb0.w);
            float4 o1 = make_float4(c[4] + bb1.x, c[5] + bb1.y, c[6] + bb1.z, c[7] + bb1.w);
            *(float4*)(C + (size_t)row * 128 + tx * 8) = o0;
            *(float4*)(C + (size_t)row * 128 + tx * 8 + 4) = o1;
        }
    }
}

// ---------------- init: zero h_out / denom, segmax -> 0 (encoded < enc(-inf)) -----
__global__ void init_kernel(float* __restrict__ h_out, int n_h, int n_seg) {
    int i = blockIdx.x * blockDim.x + threadIdx.x;
    if (i < n_h) h_out[i] = 0.0f;
    if (i < n_seg) {
        g_segmax[i] = 0u;
        g_denom[i] = 0.0f;
    }
}

// ---------------- edge pass 1: e_out = K[src]*Q[dst]*Ee*0.25, per-head score, segmax
__global__ __launch_bounds__(256) void edge1(const int* __restrict__ ei,
                                             float* __restrict__ e_out, int E) {
    int gid = blockIdx.x * blockDim.x + threadIdx.x;
    int e = gid >> 5;
    int lane = gid & 31;
    if (e >= E) return;
    int src = __ldg(&ei[e]);
    int dst = __ldg(&ei[E + e]);

    float4 kk = *(const float4*)(g_K + (size_t)src * 128 + lane * 4);
    float4 qq = *(const float4*)(g_Q + (size_t)dst * 128 + lane * 4);
    float4 ee = *(const float4*)(g_Ee + (size_t)e * 128 + lane * 4);
    float4 p;
    p.x = kk.x * qq.x * ee.x * 0.25f;
    p.y = kk.y * qq.y * ee.y * 0.25f;
    p.z = kk.z * qq.z * ee.z * 0.25f;
    p.w = kk.w * qq.w * ee.w * 0.25f;
    *(float4*)(e_out + (size_t)e * 128 + lane * 4) = p;

    float s = p.x + p.y + p.z + p.w;
    s += __shfl_xor_sync(0xffffffffu, s, 1);
    s += __shfl_xor_sync(0xffffffffu, s, 2);
    if ((lane & 3) == 0) {
        int h = lane >> 2;
        g_score[(size_t)e * 8 + h] = s;
        atomicMax(&g_segmax[(size_t)src * 8 + h], enc_f(s));
    }
}

// ---------------- edge pass 2: ex = exp(score - segmax[src]); denom += ex ---------
__global__ __launch_bounds__(256) void edge2(const int* __restrict__ ei, int E) {
    int t = blockIdx.x * blockDim.x + threadIdx.x;
    if (t >= E * 8) return;
    int e = t >> 3;
    int h = t & 7;
    int src = __ldg(&ei[e]);
    float m = dec_f(g_segmax[(size_t)src * 8 + h]);
    float ex = __expf(g_score[t] - m);
    g_ex[t] = ex;
    atomicAdd(&g_denom[(size_t)src * 8 + h], ex);
}

// ---------------- edge pass 3: h_out[src] += (ex/denom) * V[dst] ------------------
__global__ __launch_bounds__(256) void edge3(const int* __restrict__ ei,
                                             float* __restrict__ h_out, int E) {
    int gid = blockIdx.x * blockDim.x + threadIdx.x;
    int e = gid >> 5;
    int lane = gid & 31;
    if (e >= E) return;
    int src = __ldg(&ei[e]);
    int dst = __ldg(&ei[E + e]);
    int h = lane >> 2;
    float w = g_ex[(size_t)e * 8 + h] / g_denom[(size_t)src * 8 + h];
    float4 v = *(const float4*)(g_V + (size_t)dst * 128 + lane * 4);
    float* p = h_out + (size_t)src * 128 + lane * 4;
    asm volatile("red.global.add.v4.f32 [%0], {%1, %2, %3, %4};" ::"l"(p), "f"(w * v.x),
                 "f"(w * v.y), "f"(w * v.z), "f"(w * v.w)
                 : "memory");
}

// ---------------- launch ----------------
extern "C" void kernel_launch(void* const* d_in, const int* in_sizes, int n_in,
                              void* d_out, int out_size) {
    const float* x = (const float*)d_in[0];
    const float* e = (const float*)d_in[1];
    const int* ei = (const int*)d_in[2];
    const float* Wq = (const float*)d_in[3];
    const float* bq = (const float*)d_in[4];
    const float* Wk = (const float*)d_in[5];
    const float* bk = (const float*)d_in[6];
    const float* Wv = (const float*)d_in[7];
    const float* bv = (const float*)d_in[8];
    const float* We = (const float*)d_in[9];
    const float* be = (const float*)d_in[10];

    int N = in_sizes[0] / 128;
    int E = in_sizes[1] / 128;
    if (N > NN || E > NE) return;

    float* h_out = (float*)d_out;
    float* e_out = h_out + (size_t)N * 128;

    // resolve scratch symbol addresses (host-side queries; capture-safe)
    void *pQ, *pK, *pV, *pE;
    cudaGetSymbolAddress(&pQ, g_Q);
    cudaGetSymbolAddress(&pK, g_K);
    cudaGetSymbolAddress(&pV, g_V);
    cudaGetSymbolAddress(&pE, g_Ee);

    cudaFuncSetAttribute(gemm128, cudaFuncAttributeMaxDynamicSharedMemorySize,
                         GEMM_SMEM_BYTES);

    int initN = N * 128;
    init_kernel<<<(initN + 255) / 256, 256>>>(h_out, initN, N * 8);

    int nb = (N + 127) / 128;
    int eb = (E + 127) / 128;
    gemm128<<<nb, 256, GEMM_SMEM_BYTES>>>(x, Wq, bq, (float*)pQ, N);
    gemm128<<<nb, 256, GEMM_SMEM_BYTES>>>(x, Wk, bk, (float*)pK, N);
    gemm128<<<nb, 256, GEMM_SMEM_BYTES>>>(x, Wv, bv, (float*)pV, N);
    gemm128<<<eb, 256, GEMM_SMEM_BYTES>>>(e, We, be, (float*)pE, E);

    int warps_grid = (E * 32 + 255) / 256;
    edge1<<<warps_grid, 256>>>(ei, e_out, E);
    edge2<<<(E * 8 + 255) / 256, 256>>>(ei, E);
    edge3<<<warps_grid, 256>>>(ei, h_out, E);
}